// round 1
// baseline (speedup 1.0000x reference)
#include <cuda_runtime.h>
#include <cuda_fp16.h>
#include <cstdint>

// Problem constants
#define BB 2
#define CC 256
#define HH 64
#define WW 64
#define HWC (HH*WW)          // 4096
#define NQ (BB*HWC)          // 8192
#define NLVL 4
#define RAD 4

// Scratch (device globals; allocation-free rule)
__device__ float  g_f1t[BB*HWC*CC];              // (B, HW, C) fp32, 8 MB
__device__ __half g_f2p0[BB*64*64*CC];           // level 0, 4 MB
__device__ __half g_f2p1[BB*32*32*CC];           // 1 MB
__device__ __half g_f2p2[BB*16*16*CC];           // 256 KB
__device__ __half g_f2p3[BB*8*8*CC];             // 64 KB

__device__ __forceinline__ __half* level_ptr(int l) {
    switch (l) {
        case 0: return g_f2p0;
        case 1: return g_f2p1;
        case 2: return g_f2p2;
        default: return g_f2p3;
    }
}

// ---------------------------------------------------------------------------
// Transpose fmap1 (B,C,HW) -> (B,HW,C) fp32
// ---------------------------------------------------------------------------
__global__ void transpose_f1_kernel(const float* __restrict__ in) {
    __shared__ float tile[32][33];
    int b   = blockIdx.z;
    int hw0 = blockIdx.x * 32;
    int c0  = blockIdx.y * 32;
    int tx = threadIdx.x, ty = threadIdx.y;   // block (32, 8)
#pragma unroll
    for (int i = 0; i < 32; i += 8)
        tile[ty + i][tx] = in[(b*CC + c0 + ty + i) * HWC + hw0 + tx];
    __syncthreads();
#pragma unroll
    for (int i = 0; i < 32; i += 8)
        g_f1t[(b*HWC + hw0 + ty + i) * CC + c0 + tx] = tile[tx][ty + i];
}

// Transpose fmap2 (B,C,HW) -> (B,HW,C) fp16 (pyramid level 0)
__global__ void transpose_f2_kernel(const float* __restrict__ in) {
    __shared__ float tile[32][33];
    int b   = blockIdx.z;
    int hw0 = blockIdx.x * 32;
    int c0  = blockIdx.y * 32;
    int tx = threadIdx.x, ty = threadIdx.y;
#pragma unroll
    for (int i = 0; i < 32; i += 8)
        tile[ty + i][tx] = in[(b*CC + c0 + ty + i) * HWC + hw0 + tx];
    __syncthreads();
#pragma unroll
    for (int i = 0; i < 32; i += 8)
        g_f2p0[(b*HWC + hw0 + ty + i) * CC + c0 + tx] =
            __float2half_rn(tile[tx][ty + i]);
}

// ---------------------------------------------------------------------------
// 2x2 mean pool of an fp16 (B, Wl*Wl, C) level  ->  next level
// One thread per half2 output element.
// ---------------------------------------------------------------------------
__global__ void pool_kernel(int lin) {
    const __half2* in  = (const __half2*)level_ptr(lin);
    __half2*       out = (__half2*)level_ptr(lin + 1);
    int Wi = 64 >> lin;
    int Wo = Wi >> 1;
    int total = BB * Wo * Wo * (CC / 2);
    int idx = blockIdx.x * blockDim.x + threadIdx.x;
    if (idx >= total) return;
    int c2 = idx & (CC/2 - 1);
    int j  = (idx >> 7) % (Wo * Wo);
    int b  = idx / ((CC/2) * Wo * Wo);
    int Y = j / Wo, X = j % Wo;
    const __half2* base = in + (size_t)b * Wi * Wi * (CC/2);
    float2 a = __half22float2(base[((2*Y    )*Wi + 2*X    ) * (CC/2) + c2]);
    float2 bb = __half22float2(base[((2*Y    )*Wi + 2*X + 1) * (CC/2) + c2]);
    float2 c = __half22float2(base[((2*Y + 1)*Wi + 2*X    ) * (CC/2) + c2]);
    float2 d = __half22float2(base[((2*Y + 1)*Wi + 2*X + 1) * (CC/2) + c2]);
    out[idx] = __floats2half2_rn(0.25f * (a.x + bb.x + c.x + d.x),
                                 0.25f * (a.y + bb.y + c.y + d.y));
}

// ---------------------------------------------------------------------------
// Sampling kernel: one block (256 threads) per query.
//   - 32 groups of 8 lanes; each group computes one tap dot (256 ch):
//     lane owns 32 channels (4 x uint4 = 32 halves), shfl-reduce over 8 lanes.
//   - 10x10 integer tap grid in shared, then 81 bilinear outputs.
// ---------------------------------------------------------------------------
__global__ __launch_bounds__(256)
void corr_sample_kernel(const float* __restrict__ coords,
                        float* __restrict__ out) {
    __shared__ float sT[10][11];

    int n  = blockIdx.x;            // query index in [0, 8192)
    int b  = n >> 12;
    int hw = n & 4095;
    int tid = threadIdx.x;
    int sub = tid & 7;              // lane within 8-lane group
    int grp = tid >> 3;             // group id 0..31

    // This thread's 32 f1 channels, kept in registers for the whole block
    float rf1[32];
    {
        const float4* f1v = (const float4*)(g_f1t + (size_t)n * CC + sub * 32);
#pragma unroll
        for (int u = 0; u < 8; u++) {
            float4 v = f1v[u];
            rf1[u*4+0] = v.x; rf1[u*4+1] = v.y;
            rf1[u*4+2] = v.z; rf1[u*4+3] = v.w;
        }
    }

    float xq = coords[(b*2 + 0) * HWC + hw];
    float yq = coords[(b*2 + 1) * HWC + hw];

#pragma unroll
    for (int l = 0; l < NLVL; l++) {
        int   Wl    = 64 >> l;
        float scale = 1.0f / (float)(1 << l);
        float xc = xq * scale, yc = yq * scale;
        float fxf = floorf(xc), fyf = floorf(yc);
        int   bx = (int)fxf - RAD, by = (int)fyf - RAD;
        float fx = xc - fxf, fy = yc - fyf;

        const __half* f2l = level_ptr(l) + (size_t)b * Wl * Wl * CC;

        for (int t = grp; t < 100; t += 32) {
            int ix = bx + t % 10;
            int iy = by + t / 10;
            float acc = 0.f;
            if (ix >= 0 && ix < Wl && iy >= 0 && iy < Wl) {
                const uint4* p =
                    (const uint4*)(f2l + ((size_t)iy * Wl + ix) * CC + sub * 32);
#pragma unroll
                for (int u = 0; u < 4; u++) {
                    uint4 h8 = p[u];
                    float2 f;
                    f = __half22float2(*(const __half2*)&h8.x);
                    acc = fmaf(rf1[u*8+0], f.x, acc);
                    acc = fmaf(rf1[u*8+1], f.y, acc);
                    f = __half22float2(*(const __half2*)&h8.y);
                    acc = fmaf(rf1[u*8+2], f.x, acc);
                    acc = fmaf(rf1[u*8+3], f.y, acc);
                    f = __half22float2(*(const __half2*)&h8.z);
                    acc = fmaf(rf1[u*8+4], f.x, acc);
                    acc = fmaf(rf1[u*8+5], f.y, acc);
                    f = __half22float2(*(const __half2*)&h8.w);
                    acc = fmaf(rf1[u*8+6], f.x, acc);
                    acc = fmaf(rf1[u*8+7], f.y, acc);
                }
            }
            // reduce across the 8 contiguous lanes of this group
            acc += __shfl_down_sync(0xffffffffu, acc, 4);
            acc += __shfl_down_sync(0xffffffffu, acc, 2);
            acc += __shfl_down_sync(0xffffffffu, acc, 1);
            if (sub == 0) sT[t / 10][t % 10] = acc * 0.0625f;  // 1/sqrt(256)
        }
        __syncthreads();

        if (tid < 81) {
            int cx = tid / 9;   // x-offset index (reference adds dy-grid to x)
            int ry = tid % 9;   // y-offset index
            float v00 = sT[ry    ][cx    ];
            float v01 = sT[ry    ][cx + 1];
            float v10 = sT[ry + 1][cx    ];
            float v11 = sT[ry + 1][cx + 1];
            float v = (1.f - fy) * ((1.f - fx) * v00 + fx * v01)
                    +        fy  * ((1.f - fx) * v10 + fx * v11);
            out[((size_t)(b * 324 + l * 81 + tid)) * HWC + hw] = v;
        }
        __syncthreads();
    }
}

// ---------------------------------------------------------------------------
extern "C" void kernel_launch(void* const* d_in, const int* in_sizes, int n_in,
                              void* d_out, int out_size) {
    const float* fmap1  = (const float*)d_in[0];
    const float* fmap2  = (const float*)d_in[1];
    const float* coords = (const float*)d_in[2];
    float* out = (float*)d_out;

    dim3 tgrid(HWC / 32, CC / 32, BB);   // (128, 8, 2)
    dim3 tblk(32, 8);
    transpose_f1_kernel<<<tgrid, tblk>>>(fmap1);
    transpose_f2_kernel<<<tgrid, tblk>>>(fmap2);

    // pyramid levels 1..3
    {
        int Wo1 = 32, Wo2 = 16, Wo3 = 8;
        int t1 = BB * Wo1 * Wo1 * (CC/2);
        int t2 = BB * Wo2 * Wo2 * (CC/2);
        int t3 = BB * Wo3 * Wo3 * (CC/2);
        pool_kernel<<<(t1 + 255) / 256, 256>>>(0);
        pool_kernel<<<(t2 + 255) / 256, 256>>>(1);
        pool_kernel<<<(t3 + 255) / 256, 256>>>(2);
    }

    corr_sample_kernel<<<NQ, 256>>>(coords, out);
}

// round 2
// speedup vs baseline: 1.2868x; 1.2868x over previous
#include <cuda_runtime.h>
#include <cuda_fp16.h>
#include <cstdint>

// Problem constants
#define BB 2
#define CC 256
#define HH 64
#define WW 64
#define HWC (HH*WW)          // 4096
#define NQ (BB*HWC)          // 8192
#define NLVL 4
#define RAD 4
#define QT 16                // queries per tile (row strip of 16 consecutive hw)

// Scratch (device globals; allocation-free rule)
__device__ float  g_f1t[BB*HWC*CC];              // (B, HW, C) fp32, 8 MB
__device__ __half g_f2p0[BB*64*64*CC];           // level 0, 4 MB
__device__ __half g_f2p1[BB*32*32*CC];           // 1 MB
__device__ __half g_f2p2[BB*16*16*CC];           // 256 KB
__device__ __half g_f2p3[BB*8*8*CC];             // 64 KB

__device__ __forceinline__ __half* level_ptr(int l) {
    switch (l) {
        case 0: return g_f2p0;
        case 1: return g_f2p1;
        case 2: return g_f2p2;
        default: return g_f2p3;
    }
}

// ---------------------------------------------------------------------------
// Transpose fmap1 (B,C,HW) -> (B,HW,C) fp32
// ---------------------------------------------------------------------------
__global__ void transpose_f1_kernel(const float* __restrict__ in) {
    __shared__ float tile[32][33];
    int b   = blockIdx.z;
    int hw0 = blockIdx.x * 32;
    int c0  = blockIdx.y * 32;
    int tx = threadIdx.x, ty = threadIdx.y;   // block (32, 8)
#pragma unroll
    for (int i = 0; i < 32; i += 8)
        tile[ty + i][tx] = in[(b*CC + c0 + ty + i) * HWC + hw0 + tx];
    __syncthreads();
#pragma unroll
    for (int i = 0; i < 32; i += 8)
        g_f1t[(b*HWC + hw0 + ty + i) * CC + c0 + tx] = tile[tx][ty + i];
}

// Transpose fmap2 (B,C,HW) -> (B,HW,C) fp16 (pyramid level 0)
__global__ void transpose_f2_kernel(const float* __restrict__ in) {
    __shared__ float tile[32][33];
    int b   = blockIdx.z;
    int hw0 = blockIdx.x * 32;
    int c0  = blockIdx.y * 32;
    int tx = threadIdx.x, ty = threadIdx.y;
#pragma unroll
    for (int i = 0; i < 32; i += 8)
        tile[ty + i][tx] = in[(b*CC + c0 + ty + i) * HWC + hw0 + tx];
    __syncthreads();
#pragma unroll
    for (int i = 0; i < 32; i += 8)
        g_f2p0[(b*HWC + hw0 + ty + i) * CC + c0 + tx] =
            __float2half_rn(tile[tx][ty + i]);
}

// ---------------------------------------------------------------------------
// 2x2 mean pool of an fp16 (B, Wl*Wl, C) level  ->  next level
// ---------------------------------------------------------------------------
__global__ void pool_kernel(int lin) {
    const __half2* in  = (const __half2*)level_ptr(lin);
    __half2*       out = (__half2*)level_ptr(lin + 1);
    int Wi = 64 >> lin;
    int Wo = Wi >> 1;
    int total = BB * Wo * Wo * (CC / 2);
    int idx = blockIdx.x * blockDim.x + threadIdx.x;
    if (idx >= total) return;
    int c2 = idx & (CC/2 - 1);
    int j  = (idx >> 7) % (Wo * Wo);
    int b  = idx / ((CC/2) * Wo * Wo);
    int Y = j / Wo, X = j % Wo;
    const __half2* base = in + (size_t)b * Wi * Wi * (CC/2);
    float2 a  = __half22float2(base[((2*Y    )*Wi + 2*X    ) * (CC/2) + c2]);
    float2 bb = __half22float2(base[((2*Y    )*Wi + 2*X + 1) * (CC/2) + c2]);
    float2 c  = __half22float2(base[((2*Y + 1)*Wi + 2*X    ) * (CC/2) + c2]);
    float2 d  = __half22float2(base[((2*Y + 1)*Wi + 2*X + 1) * (CC/2) + c2]);
    out[idx] = __floats2half2_rn(0.25f * (a.x + bb.x + c.x + d.x),
                                 0.25f * (a.y + bb.y + c.y + d.y));
}

// ---------------------------------------------------------------------------
// Sampling kernel, tiled for L1 reuse + coalesced output.
//   grid = (512 tiles, 4 levels); block = 256 threads.
//   Tile = 16 consecutive hw (row strip). 32 groups of 8 lanes;
//   group g owns query q = g>>1, covers tap cells t = (g&1), (g&1)+2, ...
//   Each lane owns 32 channels (4 x uint4), shfl-reduce over 8 lanes.
//   All 16 tap grids staged in shared, then 81x16 coalesced outputs.
// ---------------------------------------------------------------------------
__global__ __launch_bounds__(256)
void corr_sample_kernel(const float* __restrict__ coords,
                        float* __restrict__ out) {
    __shared__ float sT[QT][110];        // [q][iy*11 + ix] tap grid (10x10, pitch 11)
    __shared__ float sX[QT], sY[QT];

    int l    = blockIdx.y;
    int bidx = blockIdx.x;               // 0..511
    int b    = bidx >> 8;                // 256 tiles per batch
    int hw0  = (bidx & 255) * QT;
    int tid  = threadIdx.x;
    int sub  = tid & 7;                  // lane within 8-lane group
    int grp  = tid >> 3;                 // 0..31
    int q    = grp >> 1;                 // query 0..15
    int half = grp & 1;

    if (tid < QT) {
        sX[tid] = coords[(b*2 + 0) * HWC + hw0 + tid];
        sY[tid] = coords[(b*2 + 1) * HWC + hw0 + tid];
    }

    // This thread's 32 f1 channels of its query (registers for whole kernel)
    float rf1[32];
    {
        int n = b * HWC + hw0 + q;
        const float4* f1v = (const float4*)(g_f1t + (size_t)n * CC + sub * 32);
#pragma unroll
        for (int u = 0; u < 8; u++) {
            float4 v = f1v[u];
            rf1[u*4+0] = v.x; rf1[u*4+1] = v.y;
            rf1[u*4+2] = v.z; rf1[u*4+3] = v.w;
        }
    }
    __syncthreads();

    int   Wl    = 64 >> l;
    float scale = 1.0f / (float)(1 << l);
    float xc = sX[q] * scale, yc = sY[q] * scale;
    float fxf = floorf(xc), fyf = floorf(yc);
    int   bx = (int)fxf - RAD, by = (int)fyf - RAD;

    const __half* f2l = level_ptr(l) + (size_t)b * Wl * Wl * CC;

    // 50 taps per group (cells t = half, half+2, ..., 98|99)
    for (int t = half; t < 100; t += 2) {
        int ix = bx + t % 10;
        int iy = by + t / 10;
        float acc = 0.f;
        if (ix >= 0 && ix < Wl && iy >= 0 && iy < Wl) {
            const uint4* p =
                (const uint4*)(f2l + ((size_t)iy * Wl + ix) * CC + sub * 32);
#pragma unroll
            for (int u = 0; u < 4; u++) {
                uint4 h8 = p[u];
                float2 f;
                f = __half22float2(*(const __half2*)&h8.x);
                acc = fmaf(rf1[u*8+0], f.x, acc);
                acc = fmaf(rf1[u*8+1], f.y, acc);
                f = __half22float2(*(const __half2*)&h8.y);
                acc = fmaf(rf1[u*8+2], f.x, acc);
                acc = fmaf(rf1[u*8+3], f.y, acc);
                f = __half22float2(*(const __half2*)&h8.z);
                acc = fmaf(rf1[u*8+4], f.x, acc);
                acc = fmaf(rf1[u*8+5], f.y, acc);
                f = __half22float2(*(const __half2*)&h8.w);
                acc = fmaf(rf1[u*8+6], f.x, acc);
                acc = fmaf(rf1[u*8+7], f.y, acc);
            }
        }
        acc += __shfl_down_sync(0xffffffffu, acc, 4);
        acc += __shfl_down_sync(0xffffffffu, acc, 2);
        acc += __shfl_down_sync(0xffffffffu, acc, 1);
        if (sub == 0) sT[q][(t / 10) * 11 + (t % 10)] = acc * 0.0625f; // 1/sqrt(C)
    }
    __syncthreads();

    // 81 outputs x 16 queries, lane -> query for 64B-coalesced stores
#pragma unroll
    for (int it = 0; it < 6; it++) {
        int idx = tid + it * 256;
        if (idx < 81 * QT) {
            int k  = idx >> 4;           // output tap 0..80
            int qq = idx & 15;
            int cx = k / 9;              // x-offset index (ref adds dy-grid to x)
            int ry = k % 9;              // y-offset index
            float xq2 = sX[qq] * scale;
            float yq2 = sY[qq] * scale;
            float fx = xq2 - floorf(xq2);
            float fy = yq2 - floorf(yq2);
            float v00 = sT[qq][ ry      * 11 + cx    ];
            float v01 = sT[qq][ ry      * 11 + cx + 1];
            float v10 = sT[qq][(ry + 1) * 11 + cx    ];
            float v11 = sT[qq][(ry + 1) * 11 + cx + 1];
            float v = (1.f - fy) * ((1.f - fx) * v00 + fx * v01)
                    +        fy  * ((1.f - fx) * v10 + fx * v11);
            out[((size_t)(b * 324 + l * 81 + k)) * HWC + hw0 + qq] = v;
        }
    }
}

// ---------------------------------------------------------------------------
extern "C" void kernel_launch(void* const* d_in, const int* in_sizes, int n_in,
                              void* d_out, int out_size) {
    const float* fmap1  = (const float*)d_in[0];
    const float* fmap2  = (const float*)d_in[1];
    const float* coords = (const float*)d_in[2];
    float* out = (float*)d_out;

    dim3 tgrid(HWC / 32, CC / 32, BB);   // (128, 8, 2)
    dim3 tblk(32, 8);
    transpose_f1_kernel<<<tgrid, tblk>>>(fmap1);
    transpose_f2_kernel<<<tgrid, tblk>>>(fmap2);

    {
        int t1 = BB * 32 * 32 * (CC/2);
        int t2 = BB * 16 * 16 * (CC/2);
        int t3 = BB * 8  * 8  * (CC/2);
        pool_kernel<<<(t1 + 255) / 256, 256>>>(0);
        pool_kernel<<<(t2 + 255) / 256, 256>>>(1);
        pool_kernel<<<(t3 + 255) / 256, 256>>>(2);
    }

    dim3 sgrid(NQ / QT, NLVL);           // (512, 4)
    corr_sample_kernel<<<sgrid, 256>>>(coords, out);
}